// round 4
// baseline (speedup 1.0000x reference)
#include <cuda_runtime.h>
#include <cuda_bf16.h>
#include <math.h>

#define N_NODES 50000
#define N_EDGES 640000
#define FEAT    128
#define HIDDEN  512
#define BATCH   32

// ---------------- scratch (static device globals; no allocation) ----------------
__device__ float g_msg[(size_t)N_NODES * FEAT];    // (h @ W_rel)
__device__ float g_root[(size_t)N_NODES * FEAT];   // (h @ W_root)
__device__ float g_h[(size_t)N_NODES * FEAT];      // layer output
__device__ int   g_eidx[2 * N_EDGES];              // int32 src|dst after conversion
__device__ int   g_is64;                           // detected input dtype flag
__device__ int   g_degi[N_NODES];
__device__ int   g_rowstart[N_NODES + 1];
__device__ int   g_cursor[N_NODES];
__device__ int   g_csr[N_EDGES];
__device__ float g_me[BATCH * FEAT];
__device__ float g_stats[64];                      // [0..31]=colmax, [32..63]=log(sumexp)

// ---------------- dtype detect + convert ----------------
// If edge_index is int64 (values < 2^31), every odd 32-bit word of the raw
// buffer is zero. Sample 2048 pairs; all-zero odd words => int64, else int32.
__global__ void k_detect(const unsigned int* __restrict__ raw) {
    __shared__ int any_nz;
    if (threadIdx.x == 0) any_nz = 0;
    __syncthreads();
    int nz = 0;
    for (int p = threadIdx.x; p < 2048; p += 256)
        if (raw[2 * p + 1] != 0u) nz = 1;
    if (nz) atomicOr(&any_nz, 1);
    __syncthreads();
    if (threadIdx.x == 0) g_is64 = any_nz ? 0 : 1;
}

__global__ void k_convert(const void* __restrict__ raw) {
    int e = blockIdx.x * blockDim.x + threadIdx.x;
    if (e >= 2 * N_EDGES) return;
    long long v;
    if (g_is64) v = ((const long long*)raw)[e];
    else        v = (long long)(((const int*)raw)[e]);
    int iv = (int)v;
    if (iv < 0) iv = 0;
    if (iv >= N_NODES) iv = N_NODES - 1;
    g_eidx[e] = iv;
}

// ---------------- CSR build ----------------
__global__ void k_zero_deg() {
    int i = blockIdx.x * blockDim.x + threadIdx.x;
    if (i < N_NODES) g_degi[i] = 0;
}

__global__ void k_count() {
    int e = blockIdx.x * blockDim.x + threadIdx.x;
    if (e < N_EDGES) atomicAdd(&g_degi[g_eidx[N_EDGES + e]], 1);
}

// single-block exclusive scan: each thread owns a contiguous chunk
__global__ void k_scan() {
    const int CH = (N_NODES + 1023) / 1024;   // 49
    int tid = threadIdx.x;
    int start = tid * CH;
    int sum = 0;
    for (int k = 0; k < CH; ++k) {
        int i = start + k;
        if (i < N_NODES) sum += g_degi[i];
    }
    int lane = tid & 31, wid = tid >> 5;
    int v = sum;
    #pragma unroll
    for (int off = 1; off < 32; off <<= 1) {
        int t = __shfl_up_sync(0xffffffffu, v, off);
        if (lane >= off) v += t;
    }
    __shared__ int wsum[32];
    if (lane == 31) wsum[wid] = v;
    __syncthreads();
    if (wid == 0) {
        int w = wsum[lane];
        #pragma unroll
        for (int off = 1; off < 32; off <<= 1) {
            int t = __shfl_up_sync(0xffffffffu, w, off);
            if (lane >= off) w += t;
        }
        wsum[lane] = w;
    }
    __syncthreads();
    int excl = v - sum + (wid > 0 ? wsum[wid - 1] : 0);
    int run = excl;
    for (int k = 0; k < CH; ++k) {
        int i = start + k;
        if (i < N_NODES) {
            g_rowstart[i] = run;
            g_cursor[i]   = run;
            run += g_degi[i];
        }
    }
    if (tid == 1023) g_rowstart[N_NODES] = run;
}

__global__ void k_fill() {
    int e = blockIdx.x * blockDim.x + threadIdx.x;
    if (e < N_EDGES) {
        int d = g_eidx[N_EDGES + e];
        int pos = atomicAdd(&g_cursor[d], 1);
        if (pos >= 0 && pos < N_EDGES) g_csr[pos] = g_eidx[e];
    }
}

// ---------------- SGEMM: C[M x 128] = A[M x 128] @ W[128 x 128] ----------------
// a_sel: 0 -> use Aext, 1 -> use g_h.  c_sel: 0 -> g_msg, 1 -> g_root.
__global__ __launch_bounds__(256) void k_sgemm128(
    const float* __restrict__ Aext, const float* __restrict__ W,
    int a_sel, int c_sel, int M)
{
    const float* A = a_sel ? (const float*)g_h : Aext;
    float*       C = c_sel ? g_root : g_msg;

    __shared__ float As[16][128];   // transposed: As[k][row]
    __shared__ float Bs[16][128];
    const int tid  = threadIdx.x;
    const int row0 = blockIdx.x * 128;
    const int tr   = (tid >> 4) * 8;
    const int tc   = (tid & 15) * 8;
    float acc[8][8];
    #pragma unroll
    for (int i = 0; i < 8; ++i)
        #pragma unroll
        for (int j = 0; j < 8; ++j) acc[i][j] = 0.f;

    const int a_r = tid >> 2;
    const int a_c = (tid & 3) * 4;
    const int b_r = tid >> 5;
    const int b_c = (tid & 31) * 4;

    for (int k0 = 0; k0 < 128; k0 += 16) {
        #pragma unroll
        for (int h = 0; h < 2; ++h) {
            int r  = a_r + h * 64;
            int gr = row0 + r;
            float4 v = make_float4(0.f, 0.f, 0.f, 0.f);
            if (gr < M) v = *(const float4*)&A[(size_t)gr * 128 + k0 + a_c];
            As[a_c + 0][r] = v.x;
            As[a_c + 1][r] = v.y;
            As[a_c + 2][r] = v.z;
            As[a_c + 3][r] = v.w;
        }
        #pragma unroll
        for (int h = 0; h < 2; ++h) {
            int r = b_r + h * 8;
            *(float4*)&Bs[r][b_c] = *(const float4*)&W[(size_t)(k0 + r) * 128 + b_c];
        }
        __syncthreads();
        #pragma unroll
        for (int k = 0; k < 16; ++k) {
            float ra[8], rb[8];
            *(float4*)&ra[0] = *(const float4*)&As[k][tr];
            *(float4*)&ra[4] = *(const float4*)&As[k][tr + 4];
            *(float4*)&rb[0] = *(const float4*)&Bs[k][tc];
            *(float4*)&rb[4] = *(const float4*)&Bs[k][tc + 4];
            #pragma unroll
            for (int i = 0; i < 8; ++i)
                #pragma unroll
                for (int j = 0; j < 8; ++j)
                    acc[i][j] += ra[i] * rb[j];
        }
        __syncthreads();
    }
    #pragma unroll
    for (int i = 0; i < 8; ++i) {
        int gr = row0 + tr + i;
        if (gr < M) {
            *(float4*)&C[(size_t)gr * 128 + tc]     = make_float4(acc[i][0], acc[i][1], acc[i][2], acc[i][3]);
            *(float4*)&C[(size_t)gr * 128 + tc + 4] = make_float4(acc[i][4], acc[i][5], acc[i][6], acc[i][7]);
        }
    }
}

// ---------------- fused gather-mean + root + bias + ReLU ----------------
// warp per node, lane owns a float4 of the 128-wide row.
__global__ void k_gather_combine(const float* __restrict__ bias)
{
    int warp = (blockIdx.x * blockDim.x + threadIdx.x) >> 5;
    int lane = threadIdx.x & 31;
    if (warp >= N_NODES) return;
    int beg = g_rowstart[warp];
    int end = g_rowstart[warp + 1];
    float4 acc = make_float4(0.f, 0.f, 0.f, 0.f);
    for (int j = beg; j < end; ++j) {
        int s = g_csr[j];
        float4 v = *(const float4*)&g_msg[(size_t)s * 128 + lane * 4];
        acc.x += v.x; acc.y += v.y; acc.z += v.z; acc.w += v.w;
    }
    float invd = 1.0f / fmaxf((float)(end - beg), 1.0f);
    float4 r  = *(const float4*)&g_root[(size_t)warp * 128 + lane * 4];
    float4 bb = *(const float4*)&bias[lane * 4];
    float4 o;
    o.x = fmaxf(acc.x * invd + r.x + bb.x, 0.f);
    o.y = fmaxf(acc.y * invd + r.y + bb.y, 0.f);
    o.z = fmaxf(acc.z * invd + r.z + bb.z, 0.f);
    o.w = fmaxf(acc.w * invd + r.w + bb.w, 0.f);
    *(float4*)&g_h[(size_t)warp * 128 + lane * 4] = o;
}

// ---------------- projection: me[b][j] = lh[0,b,:] @ Wp[:,j] + bp[j] ----------------
__global__ void k_proj(const float* __restrict__ lh, const float* __restrict__ Wp,
                       const float* __restrict__ bp)
{
    int idx = blockIdx.x * blockDim.x + threadIdx.x;
    if (idx >= BATCH * 128) return;
    int b = idx >> 7, j = idx & 127;
    float acc = bp[j];
    const float* lr = &lh[(size_t)b * HIDDEN];
    #pragma unroll 8
    for (int k = 0; k < HIDDEN; ++k)
        acc += lr[k] * Wp[(size_t)k * 128 + j];
    g_me[b * 128 + j] = acc;
}

// ---------------- scores: out[i][b] = g_h[i,:] . me[b,:] ----------------
__global__ void k_scores(float* __restrict__ out)
{
    __shared__ float sme[32 * 129];
    int tid = threadIdx.x;
    for (int idx = tid; idx < 32 * 128; idx += blockDim.x) {
        int b = idx >> 7, k = idx & 127;
        sme[b * 129 + k] = g_me[idx];
    }
    __syncthreads();
    int warp = (blockIdx.x * blockDim.x + tid) >> 5;
    int lane = tid & 31;
    if (warp >= N_NODES) return;
    const float* hr = &g_h[(size_t)warp * 128];
    const float* mr = &sme[lane * 129];
    float acc = 0.f;
    #pragma unroll
    for (int k4 = 0; k4 < 32; ++k4) {
        float4 v = *(const float4*)&hr[k4 * 4];
        acc += v.x * mr[k4 * 4 + 0];
        acc += v.y * mr[k4 * 4 + 1];
        acc += v.z * mr[k4 * 4 + 2];
        acc += v.w * mr[k4 * 4 + 3];
    }
    out[(size_t)warp * 32 + lane] = acc;
}

// ---------------- per-column max + log-sum-exp (block per column, deterministic) --------
__global__ void k_colstats(const float* __restrict__ sc)
{
    __shared__ float red[256];
    int b = blockIdx.x, tid = threadIdx.x;
    float m = -INFINITY;
    for (int i = tid; i < N_NODES; i += 256)
        m = fmaxf(m, sc[(size_t)i * 32 + b]);
    red[tid] = m; __syncthreads();
    for (int off = 128; off > 0; off >>= 1) {
        if (tid < off) red[tid] = fmaxf(red[tid], red[tid + off]);
        __syncthreads();
    }
    float M = red[0];
    __syncthreads();
    float s = 0.f;
    for (int i = tid; i < N_NODES; i += 256)
        s += __expf(sc[(size_t)i * 32 + b] - M);
    red[tid] = s; __syncthreads();
    for (int off = 128; off > 0; off >>= 1) {
        if (tid < off) red[tid] += red[tid + off];
        __syncthreads();
    }
    if (tid == 0) {
        g_stats[b]      = M;
        g_stats[32 + b] = logf(red[0]);
    }
}

__global__ void k_finalize(float* __restrict__ out)
{
    int i = blockIdx.x * blockDim.x + threadIdx.x;
    if (i < N_NODES * 32) {
        int b = i & 31;
        out[i] = out[i] - g_stats[b] - g_stats[32 + b];
    }
}

// ---------------- launch (kernel launches ONLY — graph-capture safe) ----------------
extern "C" void kernel_launch(void* const* d_in, const int* in_sizes, int n_in,
                              void* d_out, int out_size)
{
    const float* x       = (const float*)d_in[0];
    const void*  eidxraw = (const void*)d_in[1];
    const float* lh      = (const float*)d_in[2];
    const float* W1_rel  = (const float*)d_in[3];
    const float* W1_root = (const float*)d_in[4];
    const float* b1      = (const float*)d_in[5];
    const float* W2_rel  = (const float*)d_in[6];
    const float* W2_root = (const float*)d_in[7];
    const float* b2      = (const float*)d_in[8];
    const float* Wp      = (const float*)d_in[9];
    const float* bp      = (const float*)d_in[10];
    float*       out     = (float*)d_out;

    const int EB = (N_EDGES + 255) / 256;
    const int GEMM_G = (N_NODES + 127) / 128;
    const int WARP_G = (N_NODES * 32 + 255) / 256;

    // edge_index dtype detect + int32 conversion (clamped -> atomics always safe)
    k_detect<<<1, 256>>>((const unsigned int*)eidxraw);
    k_convert<<<(2 * N_EDGES + 255) / 256, 256>>>(eidxraw);

    // CSR build (once; both layers share the graph)
    k_zero_deg<<<(N_NODES + 255) / 256, 256>>>();
    k_count<<<EB, 256>>>();
    k_scan<<<1, 1024>>>();
    k_fill<<<EB, 256>>>();

    // layer 1: msg = x@W1_rel, root = x@W1_root
    k_sgemm128<<<GEMM_G, 256>>>(x, W1_rel,  0, 0, N_NODES);
    k_sgemm128<<<GEMM_G, 256>>>(x, W1_root, 0, 1, N_NODES);
    k_gather_combine<<<WARP_G, 256>>>(b1);

    // layer 2: msg = h@W2_rel, root = h@W2_root
    k_sgemm128<<<GEMM_G, 256>>>(x, W2_rel,  1, 0, N_NODES);
    k_sgemm128<<<GEMM_G, 256>>>(x, W2_root, 1, 1, N_NODES);
    k_gather_combine<<<WARP_G, 256>>>(b2);

    // projection + scores + log_softmax(axis=0)
    k_proj<<<16, 256>>>(lh, Wp, bp);
    k_scores<<<(N_NODES * 32 + 255) / 256, 256>>>(out);
    k_colstats<<<32, 256>>>(out);
    k_finalize<<<(N_NODES * 32 + 255) / 256, 256>>>(out);
}

// round 8
// speedup vs baseline: 1.0958x; 1.0958x over previous
#include <cuda_runtime.h>
#include <cuda_bf16.h>
#include <math.h>
#include <stdint.h>

#define N_NODES 50000
#define N_EDGES 640000
#define FEAT    128
#define HIDDEN  512
#define BATCH   32

// ---------------- scratch (static device globals; no allocation) ----------------
__device__ float g_msg[(size_t)N_NODES * FEAT];
__device__ float g_root[(size_t)N_NODES * FEAT];
__device__ float g_h[(size_t)N_NODES * FEAT];
__device__ int   g_eidx[2 * N_EDGES];
__device__ int   g_is64;
__device__ int   g_degi[N_NODES];
__device__ int   g_rowstart[N_NODES + 1];
__device__ int   g_cursor[N_NODES];
__device__ int   g_csr[N_EDGES];
__device__ float g_me[BATCH * FEAT];
__device__ float g_stats[64];

__device__ __forceinline__ uint32_t smem_u32(const void* p) {
    uint32_t a;
    asm("{ .reg .u64 t; cvta.to.shared.u64 t, %1; cvt.u32.u64 %0, t; }" : "=r"(a) : "l"(p));
    return a;
}

// ---------------- dtype detect + convert ----------------
__global__ void k_detect(const unsigned int* __restrict__ raw) {
    __shared__ int any_nz;
    if (threadIdx.x == 0) any_nz = 0;
    __syncthreads();
    int nz = 0;
    for (int p = threadIdx.x; p < 2048; p += 256)
        if (raw[2 * p + 1] != 0u) nz = 1;
    if (nz) atomicOr(&any_nz, 1);
    __syncthreads();
    if (threadIdx.x == 0) g_is64 = any_nz ? 0 : 1;
}

__global__ void k_convert(const void* __restrict__ raw) {
    int e = blockIdx.x * blockDim.x + threadIdx.x;
    if (e >= 2 * N_EDGES) return;
    long long v;
    if (g_is64) v = ((const long long*)raw)[e];
    else        v = (long long)(((const int*)raw)[e]);
    int iv = (int)v;
    if (iv < 0) iv = 0;
    if (iv >= N_NODES) iv = N_NODES - 1;
    g_eidx[e] = iv;
}

// ---------------- CSR build ----------------
__global__ void k_zero_deg() {
    int i = blockIdx.x * blockDim.x + threadIdx.x;
    if (i < N_NODES) g_degi[i] = 0;
}
__global__ void k_count() {
    int e = blockIdx.x * blockDim.x + threadIdx.x;
    if (e < N_EDGES) atomicAdd(&g_degi[g_eidx[N_EDGES + e]], 1);
}
__global__ void k_scan() {
    const int CH = (N_NODES + 1023) / 1024;
    int tid = threadIdx.x;
    int start = tid * CH;
    int sum = 0;
    for (int k = 0; k < CH; ++k) {
        int i = start + k;
        if (i < N_NODES) sum += g_degi[i];
    }
    int lane = tid & 31, wid = tid >> 5;
    int v = sum;
    #pragma unroll
    for (int off = 1; off < 32; off <<= 1) {
        int t = __shfl_up_sync(0xffffffffu, v, off);
        if (lane >= off) v += t;
    }
    __shared__ int wsum[32];
    if (lane == 31) wsum[wid] = v;
    __syncthreads();
    if (wid == 0) {
        int w = wsum[lane];
        #pragma unroll
        for (int off = 1; off < 32; off <<= 1) {
            int t = __shfl_up_sync(0xffffffffu, w, off);
            if (lane >= off) w += t;
        }
        wsum[lane] = w;
    }
    __syncthreads();
    int excl = v - sum + (wid > 0 ? wsum[wid - 1] : 0);
    int run = excl;
    for (int k = 0; k < CH; ++k) {
        int i = start + k;
        if (i < N_NODES) {
            g_rowstart[i] = run;
            g_cursor[i]   = run;
            run += g_degi[i];
        }
    }
    if (tid == 1023) g_rowstart[N_NODES] = run;
}
__global__ void k_fill() {
    int e = blockIdx.x * blockDim.x + threadIdx.x;
    if (e < N_EDGES) {
        int d = g_eidx[N_EDGES + e];
        int pos = atomicAdd(&g_cursor[d], 1);
        if (pos >= 0 && pos < N_EDGES) g_csr[pos] = g_eidx[e];
    }
}

// ---------------- mma.sync helpers ----------------
__device__ __forceinline__ void hmma16816(float* c, uint32_t a0, uint32_t a1,
                                          uint32_t a2, uint32_t a3,
                                          uint32_t b0, uint32_t b1) {
    asm volatile(
        "mma.sync.aligned.m16n8k16.row.col.f32.bf16.bf16.f32 "
        "{%0,%1,%2,%3}, {%4,%5,%6,%7}, {%8,%9}, {%0,%1,%2,%3};"
        : "+f"(c[0]), "+f"(c[1]), "+f"(c[2]), "+f"(c[3])
        : "r"(a0), "r"(a1), "r"(a2), "r"(a3), "r"(b0), "r"(b1));
}
__device__ __forceinline__ void ldsm_x4(uint32_t& r0, uint32_t& r1, uint32_t& r2,
                                        uint32_t& r3, uint32_t addr) {
    asm volatile("ldmatrix.sync.aligned.m8n8.x4.shared.b16 {%0,%1,%2,%3}, [%4];"
                 : "=r"(r0), "=r"(r1), "=r"(r2), "=r"(r3) : "r"(addr));
}
__device__ __forceinline__ void ldsm_x2t(uint32_t& r0, uint32_t& r1, uint32_t addr) {
    asm volatile("ldmatrix.sync.aligned.m8n8.x2.trans.shared.b16 {%0,%1}, [%2];"
                 : "=r"(r0), "=r"(r1) : "r"(addr));
}
__device__ __forceinline__ void split_bf16(float v, __nv_bfloat16& h, __nv_bfloat16& l) {
    h = __float2bfloat16(v);
    l = __float2bfloat16(v - __bfloat162float(h));
}

// ---------------- tensor-core GEMM: C = A @ W for W_rel and W_root ----------------
// 8 warps; warp w owns rows [w*16, w*16+16), all 128 cols. K chunked by 32.
// bf16 split: hi*hi + hi*lo + lo*hi, fp32 accum.
#define SP_A 40     // bf16 elems per padded A row (80 B)
#define SP_B 136    // bf16 elems per padded B row (272 B)
__global__ __launch_bounds__(256) void k_mma_gemm(
    const float* __restrict__ Aext,
    const float* __restrict__ Wrel, const float* __restrict__ Wroot,
    int a_sel, int M)
{
    __shared__ __nv_bfloat16 sA[2][128 * SP_A];   // [hi/lo][row][k-in-chunk]
    __shared__ __nv_bfloat16 sB[2][32 * SP_B];    // [hi/lo][k-in-chunk][n]

    const float* A = a_sel ? (const float*)g_h : Aext;
    int tid = threadIdx.x;
    int wid = tid >> 5, lane = tid & 31;
    int row0 = blockIdx.x * 128;
    int wrow = wid * 16;

    // ldmatrix source addresses (fixed per thread, offset per use)
    int a_lr    = lane & 7;
    int a_half  = (lane >> 3) & 1;
    int a_khalf = lane >> 4;
    uint32_t a_base = smem_u32(&sA[0][0]);
    uint32_t b_base = smem_u32(&sB[0][0]);
    const uint32_t A_IMG = 128 * SP_A * 2;   // bytes per A image
    const uint32_t B_IMG = 32 * SP_B * 2;    // bytes per B image
    // A frag addr for image i, kstep kk: row = wrow + a_lr + a_half*8, col = kk*16 + a_khalf*8
    uint32_t a_off = (uint32_t)(wrow + a_lr + a_half * 8) * (SP_A * 2) + (uint32_t)a_khalf * 16;
    // B frag addr: row = kk*16 + (lane&15), col = n*8
    int b_lr = lane & 15;

    float acc[16][4];

    #pragma unroll
    for (int pass = 0; pass < 2; ++pass) {
        const float* W = pass ? Wroot : Wrel;
        float*       C = pass ? g_root : g_msg;

        #pragma unroll
        for (int j = 0; j < 16; ++j)
            #pragma unroll
            for (int q = 0; q < 4; ++q) acc[j][q] = 0.f;

        for (int k0 = 0; k0 < 128; k0 += 32) {
            // stage A chunk: 128 rows x 32 k
            for (int idx = tid; idx < 4096; idx += 256) {
                int m = idx >> 5, kk = idx & 31;
                int gr = row0 + m;
                float v = (gr < M) ? A[(size_t)gr * 128 + k0 + kk] : 0.f;
                __nv_bfloat16 h, l;
                split_bf16(v, h, l);
                sA[0][m * SP_A + kk] = h;
                sA[1][m * SP_A + kk] = l;
            }
            // stage B chunk: 32 k x 128 n  (W is [k][n], n contiguous)
            for (int idx = tid; idx < 4096; idx += 256) {
                int kk = idx >> 7, n = idx & 127;
                float v = W[(size_t)(k0 + kk) * 128 + n];
                __nv_bfloat16 h, l;
                split_bf16(v, h, l);
                sB[0][kk * SP_B + n] = h;
                sB[1][kk * SP_B + n] = l;
            }
            __syncthreads();

            #pragma unroll
            for (int kk = 0; kk < 2; ++kk) {
                uint32_t ah0, ah1, ah2, ah3, al0, al1, al2, al3;
                ldsm_x4(ah0, ah1, ah2, ah3, a_base + 0 * A_IMG + a_off + (uint32_t)kk * 32);
                ldsm_x4(al0, al1, al2, al3, a_base + 1 * A_IMG + a_off + (uint32_t)kk * 32);
                uint32_t b_row = (uint32_t)(kk * 16 + b_lr) * (SP_B * 2);
                #pragma unroll
                for (int j = 0; j < 16; ++j) {
                    uint32_t bh0, bh1, bl0, bl1;
                    uint32_t bcol = (uint32_t)j * 16;
                    ldsm_x2t(bh0, bh1, b_base + 0 * B_IMG + b_row + bcol);
                    ldsm_x2t(bl0, bl1, b_base + 1 * B_IMG + b_row + bcol);
                    hmma16816(acc[j], ah0, ah1, ah2, ah3, bh0, bh1);
                    hmma16816(acc[j], ah0, ah1, ah2, ah3, bl0, bl1);
                    hmma16816(acc[j], al0, al1, al2, al3, bh0, bh1);
                }
            }
            __syncthreads();
        }

        // epilogue: lane g = lane>>2 (row), tig = lane&3 (col pair)
        int g   = lane >> 2;
        int tig = lane & 3;
        int r0g = row0 + wrow + g;
        int r1g = r0g + 8;
        #pragma unroll
        for (int j = 0; j < 16; ++j) {
            int col = j * 8 + tig * 2;
            if (r0g < M) *(float2*)&C[(size_t)r0g * 128 + col] = make_float2(acc[j][0], acc[j][1]);
            if (r1g < M) *(float2*)&C[(size_t)r1g * 128 + col] = make_float2(acc[j][2], acc[j][3]);
        }
        __syncthreads();
    }
}

// ---------------- fused gather-mean + root + bias + ReLU ----------------
__global__ void k_gather_combine(const float* __restrict__ bias)
{
    int warp = (blockIdx.x * blockDim.x + threadIdx.x) >> 5;
    int lane = threadIdx.x & 31;
    if (warp >= N_NODES) return;
    int beg = g_rowstart[warp];
    int end = g_rowstart[warp + 1];
    float4 acc = make_float4(0.f, 0.f, 0.f, 0.f);
    for (int j = beg; j < end; ++j) {
        int s = g_csr[j];
        float4 v = *(const float4*)&g_msg[(size_t)s * 128 + lane * 4];
        acc.x += v.x; acc.y += v.y; acc.z += v.z; acc.w += v.w;
    }
    float invd = 1.0f / fmaxf((float)(end - beg), 1.0f);
    float4 r  = *(const float4*)&g_root[(size_t)warp * 128 + lane * 4];
    float4 bb = *(const float4*)&bias[lane * 4];
    float4 o;
    o.x = fmaxf(acc.x * invd + r.x + bb.x, 0.f);
    o.y = fmaxf(acc.y * invd + r.y + bb.y, 0.f);
    o.z = fmaxf(acc.z * invd + r.z + bb.z, 0.f);
    o.w = fmaxf(acc.w * invd + r.w + bb.w, 0.f);
    *(float4*)&g_h[(size_t)warp * 128 + lane * 4] = o;
}

// ---------------- projection ----------------
__global__ void k_proj(const float* __restrict__ lh, const float* __restrict__ Wp,
                       const float* __restrict__ bp)
{
    int idx = blockIdx.x * blockDim.x + threadIdx.x;
    if (idx >= BATCH * 128) return;
    int b = idx >> 7, j = idx & 127;
    float acc = bp[j];
    const float* lr = &lh[(size_t)b * HIDDEN];
    #pragma unroll 8
    for (int k = 0; k < HIDDEN; ++k)
        acc += lr[k] * Wp[(size_t)k * 128 + j];
    g_me[b * 128 + j] = acc;
}

// ---------------- scores ----------------
__global__ void k_scores(float* __restrict__ out)
{
    __shared__ float sme[32 * 129];
    int tid = threadIdx.x;
    for (int idx = tid; idx < 32 * 128; idx += blockDim.x) {
        int b = idx >> 7, k = idx & 127;
        sme[b * 129 + k] = g_me[idx];
    }
    __syncthreads();
    int warp = (blockIdx.x * blockDim.x + tid) >> 5;
    int lane = tid & 31;
    if (warp >= N_NODES) return;
    const float* hr = &g_h[(size_t)warp * 128];
    const float* mr = &sme[lane * 129];
    float acc = 0.f;
    #pragma unroll
    for (int k4 = 0; k4 < 32; ++k4) {
        float4 v = *(const float4*)&hr[k4 * 4];
        acc += v.x * mr[k4 * 4 + 0];
        acc += v.y * mr[k4 * 4 + 1];
        acc += v.z * mr[k4 * 4 + 2];
        acc += v.w * mr[k4 * 4 + 3];
    }
    out[(size_t)warp * 32 + lane] = acc;
}

// ---------------- per-column stats + finalize ----------------
__global__ void k_colstats(const float* __restrict__ sc)
{
    __shared__ float red[256];
    int b = blockIdx.x, tid = threadIdx.x;
    float m = -INFINITY;
    for (int i = tid; i < N_NODES; i += 256)
        m = fmaxf(m, sc[(size_t)i * 32 + b]);
    red[tid] = m; __syncthreads();
    for (int off = 128; off > 0; off >>= 1) {
        if (tid < off) red[tid] = fmaxf(red[tid], red[tid + off]);
        __syncthreads();
    }
    float M = red[0];
    __syncthreads();
    float s = 0.f;
    for (int i = tid; i < N_NODES; i += 256)
        s += __expf(sc[(size_t)i * 32 + b] - M);
    red[tid] = s; __syncthreads();
    for (int off = 128; off > 0; off >>= 1) {
        if (tid < off) red[tid] += red[tid + off];
        __syncthreads();
    }
    if (tid == 0) {
        g_stats[b]      = M;
        g_stats[32 + b] = logf(red[0]);
    }
}

__global__ void k_finalize(float* __restrict__ out)
{
    int i = blockIdx.x * blockDim.x + threadIdx.x;
    if (i < N_NODES * 32) {
        int b = i & 31;
        out[i] = out[i] - g_stats[b] - g_stats[32 + b];
    }
}

// ---------------- launch ----------------
extern "C" void kernel_launch(void* const* d_in, const int* in_sizes, int n_in,
                              void* d_out, int out_size)
{
    const float* x       = (const float*)d_in[0];
    const void*  eidxraw = (const void*)d_in[1];
    const float* lh      = (const float*)d_in[2];
    const float* W1_rel  = (const float*)d_in[3];
    const float* W1_root = (const float*)d_in[4];
    const float* b1      = (const float*)d_in[5];
    const float* W2_rel  = (const float*)d_in[6];
    const float* W2_root = (const float*)d_in[7];
    const float* b2      = (const float*)d_in[8];
    const float* Wp      = (const float*)d_in[9];
    const float* bp      = (const float*)d_in[10];
    float*       out     = (float*)d_out;

    const int EB = (N_EDGES + 255) / 256;
    const int GEMM_T = (N_NODES + 127) / 128;   // 391
    const int WARP_G = (N_NODES * 32 + 255) / 256;

    k_detect<<<1, 256>>>((const unsigned int*)eidxraw);
    k_convert<<<(2 * N_EDGES + 255) / 256, 256>>>(eidxraw);

    k_zero_deg<<<(N_NODES + 255) / 256, 256>>>();
    k_count<<<EB, 256>>>();
    k_scan<<<1, 1024>>>();
    k_fill<<<EB, 256>>>();

    // layer 1: msg = x@W1_rel, root = x@W1_root (one kernel, two passes)
    k_mma_gemm<<<GEMM_T, 256>>>(x, W1_rel, W1_root, 0, N_NODES);
    k_gather_combine<<<WARP_G, 256>>>(b1);
    // layer 2
    k_mma_gemm<<<GEMM_T, 256>>>(x, W2_rel, W2_root, 1, N_NODES);
    k_gather_combine<<<WARP_G, 256>>>(b2);

    k_proj<<<16, 256>>>(lh, Wp, bp);
    k_scores<<<(N_NODES * 32 + 255) / 256, 256>>>(out);
    k_colstats<<<32, 256>>>(out);
    k_finalize<<<(N_NODES * 32 + 255) / 256, 256>>>(out);
}

// round 9
// speedup vs baseline: 1.1587x; 1.0574x over previous
#include <cuda_runtime.h>
#include <cuda_bf16.h>
#include <math.h>
#include <stdint.h>

#define N_NODES 50000
#define N_EDGES 640000
#define FEAT    128
#define HIDDEN  512
#define BATCH   32

// ---------------- scratch (static device globals; no allocation) ----------------
__device__ float g_agg[(size_t)N_NODES * FEAT];    // segment-mean of source rows
__device__ float g_h[(size_t)N_NODES * FEAT];      // layer-1 output
__device__ float g_h2[(size_t)N_NODES * FEAT];     // layer-2 output
__device__ int   g_eidx[2 * N_EDGES];
__device__ int   g_is64;
__device__ int   g_degi[N_NODES];
__device__ int   g_rowstart[N_NODES + 1];
__device__ int   g_cursor[N_NODES];
__device__ int   g_csr[N_EDGES];
__device__ float g_me[BATCH * FEAT];
__device__ float g_stats[64];

__device__ __forceinline__ uint32_t smem_u32(const void* p) {
    uint32_t a;
    asm("{ .reg .u64 t; cvta.to.shared.u64 t, %1; cvt.u32.u64 %0, t; }" : "=r"(a) : "l"(p));
    return a;
}

// ---------------- dtype detect ----------------
__global__ void k_detect(const unsigned int* __restrict__ raw) {
    __shared__ int any_nz;
    if (threadIdx.x == 0) any_nz = 0;
    __syncthreads();
    int nz = 0;
    for (int p = threadIdx.x; p < 2048; p += 256)
        if (raw[2 * p + 1] != 0u) nz = 1;
    if (nz) atomicOr(&any_nz, 1);
    __syncthreads();
    if (threadIdx.x == 0) g_is64 = any_nz ? 0 : 1;
}

__global__ void k_zero_deg() {
    int i = blockIdx.x * blockDim.x + threadIdx.x;
    if (i < N_NODES) g_degi[i] = 0;
}

// convert + count fused (deg must be zeroed first)
__global__ void k_convert_count(const void* __restrict__ raw) {
    int e = blockIdx.x * blockDim.x + threadIdx.x;
    if (e >= 2 * N_EDGES) return;
    long long v;
    if (g_is64) v = ((const long long*)raw)[e];
    else        v = (long long)(((const int*)raw)[e]);
    int iv = (int)v;
    if (iv < 0) iv = 0;
    if (iv >= N_NODES) iv = N_NODES - 1;
    g_eidx[e] = iv;
    if (e >= N_EDGES) atomicAdd(&g_degi[iv], 1);   // dst half counts degree
}

__global__ void k_scan() {
    const int CH = (N_NODES + 1023) / 1024;
    int tid = threadIdx.x;
    int start = tid * CH;
    int sum = 0;
    for (int k = 0; k < CH; ++k) {
        int i = start + k;
        if (i < N_NODES) sum += g_degi[i];
    }
    int lane = tid & 31, wid = tid >> 5;
    int v = sum;
    #pragma unroll
    for (int off = 1; off < 32; off <<= 1) {
        int t = __shfl_up_sync(0xffffffffu, v, off);
        if (lane >= off) v += t;
    }
    __shared__ int wsum[32];
    if (lane == 31) wsum[wid] = v;
    __syncthreads();
    if (wid == 0) {
        int w = wsum[lane];
        #pragma unroll
        for (int off = 1; off < 32; off <<= 1) {
            int t = __shfl_up_sync(0xffffffffu, w, off);
            if (lane >= off) w += t;
        }
        wsum[lane] = w;
    }
    __syncthreads();
    int excl = v - sum + (wid > 0 ? wsum[wid - 1] : 0);
    int run = excl;
    for (int k = 0; k < CH; ++k) {
        int i = start + k;
        if (i < N_NODES) {
            g_rowstart[i] = run;
            g_cursor[i]   = run;
            run += g_degi[i];
        }
    }
    if (tid == 1023) g_rowstart[N_NODES] = run;
}

__global__ void k_fill() {
    int e = blockIdx.x * blockDim.x + threadIdx.x;
    if (e < N_EDGES) {
        int d = g_eidx[N_EDGES + e];
        int pos = atomicAdd(&g_cursor[d], 1);
        if (pos >= 0 && pos < N_EDGES) g_csr[pos] = g_eidx[e];
    }
}

// ---------------- gather: g_agg[d] = mean over src of base[src] ----------------
// warp per node, lane owns float4. from_h: 0 -> base param (x), 1 -> g_h.
__global__ void k_gather(const float* __restrict__ base, int from_h)
{
    const float* B = from_h ? (const float*)g_h : base;
    int warp = (blockIdx.x * blockDim.x + threadIdx.x) >> 5;
    int lane = threadIdx.x & 31;
    if (warp >= N_NODES) return;
    int beg = g_rowstart[warp];
    int end = g_rowstart[warp + 1];
    float4 acc = make_float4(0.f, 0.f, 0.f, 0.f);
    for (int j = beg; j < end; ++j) {
        int s = g_csr[j];
        float4 v = *(const float4*)&B[(size_t)s * 128 + lane * 4];
        acc.x += v.x; acc.y += v.y; acc.z += v.z; acc.w += v.w;
    }
    float invd = 1.0f / fmaxf((float)(end - beg), 1.0f);
    acc.x *= invd; acc.y *= invd; acc.z *= invd; acc.w *= invd;
    *(float4*)&g_agg[(size_t)warp * 128 + lane * 4] = acc;
}

// ---------------- mma.sync helpers ----------------
__device__ __forceinline__ void hmma16816(float* c, const uint32_t* a,
                                          uint32_t b0, uint32_t b1) {
    asm volatile(
        "mma.sync.aligned.m16n8k16.row.col.f32.bf16.bf16.f32 "
        "{%0,%1,%2,%3}, {%4,%5,%6,%7}, {%8,%9}, {%0,%1,%2,%3};"
        : "+f"(c[0]), "+f"(c[1]), "+f"(c[2]), "+f"(c[3])
        : "r"(a[0]), "r"(a[1]), "r"(a[2]), "r"(a[3]), "r"(b0), "r"(b1));
}
__device__ __forceinline__ void ldsm_x4(uint32_t* r, uint32_t addr) {
    asm volatile("ldmatrix.sync.aligned.m8n8.x4.shared.b16 {%0,%1,%2,%3}, [%4];"
                 : "=r"(r[0]), "=r"(r[1]), "=r"(r[2]), "=r"(r[3]) : "r"(addr));
}
__device__ __forceinline__ void ldsm_x2t(uint32_t& r0, uint32_t& r1, uint32_t addr) {
    asm volatile("ldmatrix.sync.aligned.m8n8.x2.trans.shared.b16 {%0,%1}, [%2];"
                 : "=r"(r0), "=r"(r1) : "r"(addr));
}
__device__ __forceinline__ void split_bf16(float v, __nv_bfloat16& h, __nv_bfloat16& l) {
    h = __float2bfloat16(v);
    l = __float2bfloat16(v - __bfloat162float(h));
}

// ---------------- fused layer GEMM ----------------
// h_out = relu([agg | h_in] @ [Wrel; Wroot] + b), K=256, N=128.
// 8 warps, warp tile 32m x 64n (warp_m = wid>>1, warp_n = wid&1).
// bf16 split: hi*hi + hi*lo + lo*hi, fp32 accum.
#define SP_A 40     // padded bf16 elems per A row (80 B)
#define SP_B 136    // padded bf16 elems per B row (272 B)
__global__ __launch_bounds__(256) void k_layer_gemm(
    const float* __restrict__ Hext,
    const float* __restrict__ Wrel, const float* __restrict__ Wroot,
    const float* __restrict__ bias,
    int h_sel,       // 0: Hext, 1: g_h
    int c_sel,       // 0: write g_h, 1: write g_h2
    int M)
{
    __shared__ __nv_bfloat16 sA[2][128 * SP_A];   // [hi/lo][row][k-in-chunk]
    __shared__ __nv_bfloat16 sB[2][32 * SP_B];    // [hi/lo][k-in-chunk][n]

    const float* Hin = h_sel ? (const float*)g_h : Hext;
    float*       C   = c_sel ? g_h2 : g_h;
    int tid = threadIdx.x;
    int wid = tid >> 5, lane = tid & 31;
    int row0 = blockIdx.x * 128;
    int warp_m = wid >> 1, warp_n = wid & 1;
    int wrow = warp_m * 32;
    int wcol = warp_n * 64;

    uint32_t a_base = smem_u32(&sA[0][0]);
    uint32_t b_base = smem_u32(&sB[0][0]);
    const uint32_t A_IMG = 128 * SP_A * 2;
    const uint32_t B_IMG = 32 * SP_B * 2;
    int a_lr    = lane & 7;
    int a_half  = (lane >> 3) & 1;
    int a_khalf = lane >> 4;
    // per-thread base offset inside A image (row part w/o mb, col part w/o kk)
    uint32_t a_off0 = (uint32_t)(wrow + a_lr + a_half * 8) * (SP_A * 2) + (uint32_t)a_khalf * 16;
    int b_lr = lane & 15;

    float acc[2][8][4];
    #pragma unroll
    for (int mb = 0; mb < 2; ++mb)
        #pragma unroll
        for (int nb = 0; nb < 8; ++nb)
            #pragma unroll
            for (int q = 0; q < 4; ++q) acc[mb][nb][q] = 0.f;

    for (int c = 0; c < 8; ++c) {
        int k0 = c * 32;
        const float* Asrc = (k0 < 128) ? (const float*)g_agg : Hin;
        const float* Bsrc = (k0 < 128) ? Wrel : Wroot;
        int ka = k0 & 127;

        // stage A chunk: 128 rows x 32 k
        for (int idx = tid; idx < 4096; idx += 256) {
            int m = idx >> 5, kk = idx & 31;
            int gr = row0 + m;
            float v = (gr < M) ? Asrc[(size_t)gr * 128 + ka + kk] : 0.f;
            __nv_bfloat16 h, l;
            split_bf16(v, h, l);
            sA[0][m * SP_A + kk] = h;
            sA[1][m * SP_A + kk] = l;
        }
        // stage B chunk: 32 k x 128 n
        for (int idx = tid; idx < 4096; idx += 256) {
            int kk = idx >> 7, n = idx & 127;
            float v = Bsrc[(size_t)(ka + kk) * 128 + n];
            __nv_bfloat16 h, l;
            split_bf16(v, h, l);
            sB[0][kk * SP_B + n] = h;
            sB[1][kk * SP_B + n] = l;
        }
        __syncthreads();

        #pragma unroll
        for (int kk = 0; kk < 2; ++kk) {
            uint32_t ah[2][4], al[2][4];
            #pragma unroll
            for (int mb = 0; mb < 2; ++mb) {
                uint32_t ao = a_off0 + (uint32_t)(mb * 16) * (SP_A * 2) + (uint32_t)kk * 32;
                ldsm_x4(ah[mb], a_base + 0 * A_IMG + ao);
                ldsm_x4(al[mb], a_base + 1 * A_IMG + ao);
            }
            uint32_t b_row = (uint32_t)(kk * 16 + b_lr) * (SP_B * 2);
            #pragma unroll
            for (int nb = 0; nb < 8; ++nb) {
                uint32_t bh0, bh1, bl0, bl1;
                uint32_t bcol = (uint32_t)(wcol + nb * 8) * 2;
                ldsm_x2t(bh0, bh1, b_base + 0 * B_IMG + b_row + bcol);
                ldsm_x2t(bl0, bl1, b_base + 1 * B_IMG + b_row + bcol);
                #pragma unroll
                for (int mb = 0; mb < 2; ++mb) {
                    hmma16816(acc[mb][nb], ah[mb], bh0, bh1);
                    hmma16816(acc[mb][nb], ah[mb], bl0, bl1);
                    hmma16816(acc[mb][nb], al[mb], bh0, bh1);
                }
            }
        }
        __syncthreads();
    }

    // epilogue: + bias, relu, write
    int g   = lane >> 2;
    int tig = lane & 3;
    #pragma unroll
    for (int nb = 0; nb < 8; ++nb) {
        int col = wcol + nb * 8 + tig * 2;
        float bb0 = bias[col], bb1 = bias[col + 1];
        #pragma unroll
        for (int mb = 0; mb < 2; ++mb) {
            int r0g = row0 + wrow + mb * 16 + g;
            int r1g = r0g + 8;
            float* a = acc[mb][nb];
            if (r0g < M)
                *(float2*)&C[(size_t)r0g * 128 + col] =
                    make_float2(fmaxf(a[0] + bb0, 0.f), fmaxf(a[1] + bb1, 0.f));
            if (r1g < M)
                *(float2*)&C[(size_t)r1g * 128 + col] =
                    make_float2(fmaxf(a[2] + bb0, 0.f), fmaxf(a[3] + bb1, 0.f));
        }
    }
}

// ---------------- projection ----------------
__global__ void k_proj(const float* __restrict__ lh, const float* __restrict__ Wp,
                       const float* __restrict__ bp)
{
    int idx = blockIdx.x * blockDim.x + threadIdx.x;
    if (idx >= BATCH * 128) return;
    int b = idx >> 7, j = idx & 127;
    float acc = bp[j];
    const float* lr = &lh[(size_t)b * HIDDEN];
    #pragma unroll 8
    for (int k = 0; k < HIDDEN; ++k)
        acc += lr[k] * Wp[(size_t)k * 128 + j];
    g_me[b * 128 + j] = acc;
}

// ---------------- scores: out[i][b] = g_h2[i,:] . me[b,:] ----------------
__global__ void k_scores(float* __restrict__ out)
{
    __shared__ float sme[32 * 129];
    int tid = threadIdx.x;
    for (int idx = tid; idx < 32 * 128; idx += blockDim.x) {
        int b = idx >> 7, k = idx & 127;
        sme[b * 129 + k] = g_me[idx];
    }
    __syncthreads();
    int warp = (blockIdx.x * blockDim.x + tid) >> 5;
    int lane = tid & 31;
    if (warp >= N_NODES) return;
    const float* hr = &g_h2[(size_t)warp * 128];
    const float* mr = &sme[lane * 129];
    float acc = 0.f;
    #pragma unroll
    for (int k4 = 0; k4 < 32; ++k4) {
        float4 v = *(const float4*)&hr[k4 * 4];
        acc += v.x * mr[k4 * 4 + 0];
        acc += v.y * mr[k4 * 4 + 1];
        acc += v.z * mr[k4 * 4 + 2];
        acc += v.w * mr[k4 * 4 + 3];
    }
    out[(size_t)warp * 32 + lane] = acc;
}

// ---------------- per-column stats + finalize ----------------
__global__ void k_colstats(const float* __restrict__ sc)
{
    __shared__ float red[256];
    int b = blockIdx.x, tid = threadIdx.x;
    float m = -INFINITY;
    for (int i = tid; i < N_NODES; i += 256)
        m = fmaxf(m, sc[(size_t)i * 32 + b]);
    red[tid] = m; __syncthreads();
    for (int off = 128; off > 0; off >>= 1) {
        if (tid < off) red[tid] = fmaxf(red[tid], red[tid + off]);
        __syncthreads();
    }
    float M = red[0];
    __syncthreads();
    float s = 0.f;
    for (int i = tid; i < N_NODES; i += 256)
        s += __expf(sc[(size_t)i * 32 + b] - M);
    red[tid] = s; __syncthreads();
    for (int off = 128; off > 0; off >>= 1) {
        if (tid < off) red[tid] += red[tid + off];
        __syncthreads();
    }
    if (tid == 0) {
        g_stats[b]      = M;
        g_stats[32 + b] = logf(red[0]);
    }
}

__global__ void k_finalize(float* __restrict__ out)
{
    int i = blockIdx.x * blockDim.x + threadIdx.x;
    if (i < N_NODES * 32) {
        int b = i & 31;
        out[i] = out[i] - g_stats[b] - g_stats[32 + b];
    }
}

// ---------------- launch ----------------
extern "C" void kernel_launch(void* const* d_in, const int* in_sizes, int n_in,
                              void* d_out, int out_size)
{
    const float* x       = (const float*)d_in[0];
    const void*  eidxraw = (const void*)d_in[1];
    const float* lh      = (const float*)d_in[2];
    const float* W1_rel  = (const float*)d_in[3];
    const float* W1_root = (const float*)d_in[4];
    const float* b1      = (const float*)d_in[5];
    const float* W2_rel  = (const float*)d_in[6];
    const float* W2_root = (const float*)d_in[7];
    const float* b2      = (const float*)d_in[8];
    const float* Wp      = (const float*)d_in[9];
    const float* bp      = (const float*)d_in[10];
    float*       out     = (float*)d_out;

    const int GEMM_T = (N_NODES + 127) / 128;       // 391
    const int WARP_G = (N_NODES * 32 + 255) / 256;  // warp-per-node grids

    // CSR build
    k_zero_deg<<<(N_NODES + 255) / 256, 256>>>();
    k_detect<<<1, 256>>>((const unsigned int*)eidxraw);
    k_convert_count<<<(2 * N_EDGES + 255) / 256, 256>>>(eidxraw);
    k_scan<<<1, 1024>>>();
    k_fill<<<(N_EDGES + 255) / 256, 256>>>();

    // layer 1: agg = mean x[src]; h = relu([agg|x] @ [W1rel;W1root] + b1)
    k_gather<<<WARP_G, 256>>>(x, 0);
    k_layer_gemm<<<GEMM_T, 256>>>(x, W1_rel, W1_root, b1, 0, 0, N_NODES);

    // layer 2: agg = mean h[src]; h2 = relu([agg|h] @ [W2rel;W2root] + b2)
    k_gather<<<WARP_G, 256>>>(x, 1);
    k_layer_gemm<<<GEMM_T, 256>>>(x, W2_rel, W2_root, b2, 1, 1, N_NODES);

    // projection + scores + log_softmax(axis=0)
    k_proj<<<16, 256>>>(lh, Wp, bp);
    k_scores<<<WARP_G, 256>>>(out);
    k_colstats<<<32, 256>>>(out);
    k_finalize<<<(N_NODES * 32 + 255) / 256, 256>>>(out);
}

// round 11
// speedup vs baseline: 1.3663x; 1.1792x over previous
#include <cuda_runtime.h>
#include <cuda_bf16.h>
#include <math.h>
#include <stdint.h>

#define N_NODES 50000
#define N_EDGES 640000
#define FEAT    128
#define HIDDEN  512
#define BATCH   32

#define SCAN_B 256
#define SCAN_G ((N_NODES + SCAN_B - 1) / SCAN_B)   // 196

// ---------------- scratch (static device globals; no allocation) ----------------
__device__ float g_agg[(size_t)N_NODES * FEAT];    // segment-mean of source rows
__device__ float g_h[(size_t)N_NODES * FEAT];      // layer-1 output
__device__ float g_h2[(size_t)N_NODES * FEAT];     // layer-2 output
__device__ int   g_eidx[2 * N_EDGES];
__device__ int   g_is64;
__device__ int   g_degi[N_NODES];
__device__ int   g_bsum[SCAN_G];
__device__ int   g_boff[SCAN_G + 1];
__device__ int   g_rowstart[N_NODES + 1];
__device__ int   g_cursor[N_NODES];
__device__ int   g_csr[N_EDGES];
__device__ float g_me[BATCH * FEAT];
__device__ float g_stats[64];

__device__ __forceinline__ uint32_t smem_u32(const void* p) {
    uint32_t a;
    asm("{ .reg .u64 t; cvta.to.shared.u64 t, %1; cvt.u32.u64 %0, t; }" : "=r"(a) : "l"(p));
    return a;
}

// ---------------- dtype detect ----------------
__global__ void k_detect(const unsigned int* __restrict__ raw) {
    __shared__ int any_nz;
    if (threadIdx.x == 0) any_nz = 0;
    __syncthreads();
    int nz = 0;
    for (int p = threadIdx.x; p < 2048; p += 256)
        if (raw[2 * p + 1] != 0u) nz = 1;
    if (nz) atomicOr(&any_nz, 1);
    __syncthreads();
    if (threadIdx.x == 0) g_is64 = any_nz ? 0 : 1;
}

__global__ void k_zero_deg() {
    int i = blockIdx.x * blockDim.x + threadIdx.x;
    if (i < N_NODES) g_degi[i] = 0;
}

// convert + count fused (deg must be zeroed first)
__global__ void k_convert_count(const void* __restrict__ raw) {
    int e = blockIdx.x * blockDim.x + threadIdx.x;
    if (e >= 2 * N_EDGES) return;
    long long v;
    if (g_is64) v = ((const long long*)raw)[e];
    else        v = (long long)(((const int*)raw)[e]);
    int iv = (int)v;
    if (iv < 0) iv = 0;
    if (iv >= N_NODES) iv = N_NODES - 1;
    g_eidx[e] = iv;
    if (e >= N_EDGES) atomicAdd(&g_degi[iv], 1);   // dst half counts degree
}

// ---------------- hierarchical scan ----------------
__global__ void k_blocksum() {
    __shared__ int red[SCAN_B];
    int i = blockIdx.x * SCAN_B + threadIdx.x;
    red[threadIdx.x] = (i < N_NODES) ? g_degi[i] : 0;
    __syncthreads();
    for (int off = SCAN_B / 2; off > 0; off >>= 1) {
        if (threadIdx.x < off) red[threadIdx.x] += red[threadIdx.x + off];
        __syncthreads();
    }
    if (threadIdx.x == 0) g_bsum[blockIdx.x] = red[0];
}

__global__ void k_scanbsum() {
    // 256 threads >= SCAN_G; shared-mem Hillis-Steele over SCAN_G entries
    __shared__ int s[SCAN_B];
    int tid = threadIdx.x;
    s[tid] = (tid < SCAN_G) ? g_bsum[tid] : 0;
    __syncthreads();
    for (int off = 1; off < SCAN_B; off <<= 1) {
        int v = (tid >= off) ? s[tid - off] : 0;
        __syncthreads();
        s[tid] += v;
        __syncthreads();
    }
    if (tid < SCAN_G) g_boff[tid + 1] = s[tid];
    if (tid == 0) g_boff[0] = 0;
}

__global__ void k_scatter_rows() {
    __shared__ int wsum[8];
    int i = blockIdx.x * SCAN_B + threadIdx.x;
    int tid = threadIdx.x;
    int lane = tid & 31, wid = tid >> 5;
    int d = (i < N_NODES) ? g_degi[i] : 0;
    // warp inclusive scan
    int v = d;
    #pragma unroll
    for (int off = 1; off < 32; off <<= 1) {
        int t = __shfl_up_sync(0xffffffffu, v, off);
        if (lane >= off) v += t;
    }
    if (lane == 31) wsum[wid] = v;
    __syncthreads();
    if (wid == 0 && lane < 8) {
        int w = wsum[lane];
        #pragma unroll
        for (int off = 1; off < 8; off <<= 1) {
            int t = __shfl_up_sync(0xffu, w, off);
            if (lane >= off) w += t;
        }
        wsum[lane] = w;
    }
    __syncthreads();
    int excl = v - d + (wid > 0 ? wsum[wid - 1] : 0) + g_boff[blockIdx.x];
    if (i < N_NODES) {
        g_rowstart[i] = excl;
        g_cursor[i]   = excl;
    }
    if (i == N_NODES - 1) g_rowstart[N_NODES] = excl + d;
}

__global__ void k_fill() {
    int e = blockIdx.x * blockDim.x + threadIdx.x;
    if (e < N_EDGES) {
        int d = g_eidx[N_EDGES + e];
        int pos = atomicAdd(&g_cursor[d], 1);
        if (pos >= 0 && pos < N_EDGES) g_csr[pos] = g_eidx[e];
    }
}

// ---------------- gather: g_agg[d] = mean over src of base[src] ----------------
__global__ void k_gather(const float* __restrict__ base, int from_h)
{
    const float* B = from_h ? (const float*)g_h : base;
    int warp = (blockIdx.x * blockDim.x + threadIdx.x) >> 5;
    int lane = threadIdx.x & 31;
    if (warp >= N_NODES) return;
    int beg = g_rowstart[warp];
    int end = g_rowstart[warp + 1];
    float4 acc = make_float4(0.f, 0.f, 0.f, 0.f);
    for (int j = beg; j < end; ++j) {
        int s = g_csr[j];
        float4 v = *(const float4*)&B[(size_t)s * 128 + lane * 4];
        acc.x += v.x; acc.y += v.y; acc.z += v.z; acc.w += v.w;
    }
    float invd = 1.0f / fmaxf((float)(end - beg), 1.0f);
    acc.x *= invd; acc.y *= invd; acc.z *= invd; acc.w *= invd;
    *(float4*)&g_agg[(size_t)warp * 128 + lane * 4] = acc;
}

// ---------------- mma.sync helpers ----------------
__device__ __forceinline__ void hmma16816(float* c, const uint32_t* a,
                                          uint32_t b0, uint32_t b1) {
    asm volatile(
        "mma.sync.aligned.m16n8k16.row.col.f32.bf16.bf16.f32 "
        "{%0,%1,%2,%3}, {%4,%5,%6,%7}, {%8,%9}, {%0,%1,%2,%3};"
        : "+f"(c[0]), "+f"(c[1]), "+f"(c[2]), "+f"(c[3])
        : "r"(a[0]), "r"(a[1]), "r"(a[2]), "r"(a[3]), "r"(b0), "r"(b1));
}
__device__ __forceinline__ void ldsm_x4(uint32_t* r, uint32_t addr) {
    asm volatile("ldmatrix.sync.aligned.m8n8.x4.shared.b16 {%0,%1,%2,%3}, [%4];"
                 : "=r"(r[0]), "=r"(r[1]), "=r"(r[2]), "=r"(r[3]) : "r"(addr));
}
__device__ __forceinline__ void ldsm_x2t(uint32_t& r0, uint32_t& r1, uint32_t addr) {
    asm volatile("ldmatrix.sync.aligned.m8n8.x2.trans.shared.b16 {%0,%1}, [%2];"
                 : "=r"(r0), "=r"(r1) : "r"(addr));
}
__device__ __forceinline__ void split_bf16(float v, __nv_bfloat16& h, __nv_bfloat16& l) {
    h = __float2bfloat16(v);
    l = __float2bfloat16(v - __bfloat162float(h));
}

// ---------------- fused layer GEMM ----------------
// h_out = relu([agg | h_in] @ [Wrel; Wroot] + b), K=256, N=128.
#define SP_A 40
#define SP_B 136
__global__ __launch_bounds__(256) void k_layer_gemm(
    const float* __restrict__ Hext,
    const float* __restrict__ Wrel, const float* __restrict__ Wroot,
    const float* __restrict__ bias,
    int h_sel, int c_sel, int M)
{
    __shared__ __nv_bfloat16 sA[2][128 * SP_A];
    __shared__ __nv_bfloat16 sB[2][32 * SP_B];

    const float* Hin = h_sel ? (const float*)g_h : Hext;
    float*       C   = c_sel ? g_h2 : g_h;
    int tid = threadIdx.x;
    int wid = tid >> 5, lane = tid & 31;
    int row0 = blockIdx.x * 128;
    int warp_m = wid >> 1, warp_n = wid & 1;
    int wrow = warp_m * 32;
    int wcol = warp_n * 64;

    uint32_t a_base = smem_u32(&sA[0][0]);
    uint32_t b_base = smem_u32(&sB[0][0]);
    const uint32_t A_IMG = 128 * SP_A * 2;
    const uint32_t B_IMG = 32 * SP_B * 2;
    int a_lr    = lane & 7;
    int a_half  = (lane >> 3) & 1;
    int a_khalf = lane >> 4;
    uint32_t a_off0 = (uint32_t)(wrow + a_lr + a_half * 8) * (SP_A * 2) + (uint32_t)a_khalf * 16;
    int b_lr = lane & 15;

    float acc[2][8][4];
    #pragma unroll
    for (int mb = 0; mb < 2; ++mb)
        #pragma unroll
        for (int nb = 0; nb < 8; ++nb)
            #pragma unroll
            for (int q = 0; q < 4; ++q) acc[mb][nb][q] = 0.f;

    for (int c = 0; c < 8; ++c) {
        int k0 = c * 32;
        const float* Asrc = (k0 < 128) ? (const float*)g_agg : Hin;
        const float* Bsrc = (k0 < 128) ? Wrel : Wroot;
        int ka = k0 & 127;

        for (int idx = tid; idx < 4096; idx += 256) {
            int m = idx >> 5, kk = idx & 31;
            int gr = row0 + m;
            float v = (gr < M) ? Asrc[(size_t)gr * 128 + ka + kk] : 0.f;
            __nv_bfloat16 h, l;
            split_bf16(v, h, l);
            sA[0][m * SP_A + kk] = h;
            sA[1][m * SP_A + kk] = l;
        }
        for (int idx = tid; idx < 4096; idx += 256) {
            int kk = idx >> 7, n = idx & 127;
            float v = Bsrc[(size_t)(ka + kk) * 128 + n];
            __nv_bfloat16 h, l;
            split_bf16(v, h, l);
            sB[0][kk * SP_B + n] = h;
            sB[1][kk * SP_B + n] = l;
        }
        __syncthreads();

        #pragma unroll
        for (int kk = 0; kk < 2; ++kk) {
            uint32_t ah[2][4], al[2][4];
            #pragma unroll
            for (int mb = 0; mb < 2; ++mb) {
                uint32_t ao = a_off0 + (uint32_t)(mb * 16) * (SP_A * 2) + (uint32_t)kk * 32;
                ldsm_x4(ah[mb], a_base + 0 * A_IMG + ao);
                ldsm_x4(al[mb], a_base + 1 * A_IMG + ao);
            }
            uint32_t b_row = (uint32_t)(kk * 16 + b_lr) * (SP_B * 2);
            #pragma unroll
            for (int nb = 0; nb < 8; ++nb) {
                uint32_t bh0, bh1, bl0, bl1;
                uint32_t bcol = (uint32_t)(wcol + nb * 8) * 2;
                ldsm_x2t(bh0, bh1, b_base + 0 * B_IMG + b_row + bcol);
                ldsm_x2t(bl0, bl1, b_base + 1 * B_IMG + b_row + bcol);
                #pragma unroll
                for (int mb = 0; mb < 2; ++mb) {
                    hmma16816(acc[mb][nb], ah[mb], bh0, bh1);
                    hmma16816(acc[mb][nb], ah[mb], bl0, bl1);
                    hmma16816(acc[mb][nb], al[mb], bh0, bh1);
                }
            }
        }
        __syncthreads();
    }

    int g   = lane >> 2;
    int tig = lane & 3;
    #pragma unroll
    for (int nb = 0; nb < 8; ++nb) {
        int col = wcol + nb * 8 + tig * 2;
        float bb0 = bias[col], bb1 = bias[col + 1];
        #pragma unroll
        for (int mb = 0; mb < 2; ++mb) {
            int r0g = row0 + wrow + mb * 16 + g;
            int r1g = r0g + 8;
            float* a = acc[mb][nb];
            if (r0g < M)
                *(float2*)&C[(size_t)r0g * 128 + col] =
                    make_float2(fmaxf(a[0] + bb0, 0.f), fmaxf(a[1] + bb1, 0.f));
            if (r1g < M)
                *(float2*)&C[(size_t)r1g * 128 + col] =
                    make_float2(fmaxf(a[2] + bb0, 0.f), fmaxf(a[3] + bb1, 0.f));
        }
    }
}

// ---------------- projection ----------------
__global__ void k_proj(const float* __restrict__ lh, const float* __restrict__ Wp,
                       const float* __restrict__ bp)
{
    int idx = blockIdx.x * blockDim.x + threadIdx.x;
    if (idx >= BATCH * 128) return;
    int b = idx >> 7, j = idx & 127;
    float acc = bp[j];
    const float* lr = &lh[(size_t)b * HIDDEN];
    #pragma unroll 8
    for (int k = 0; k < HIDDEN; ++k)
        acc += lr[k] * Wp[(size_t)k * 128 + j];
    g_me[b * 128 + j] = acc;
}

// ---------------- scores ----------------
__global__ void k_scores(float* __restrict__ out)
{
    __shared__ float sme[32 * 129];
    int tid = threadIdx.x;
    for (int idx = tid; idx < 32 * 128; idx += blockDim.x) {
        int b = idx >> 7, k = idx & 127;
        sme[b * 129 + k] = g_me[idx];
    }
    __syncthreads();
    int warp = (blockIdx.x * blockDim.x + tid) >> 5;
    int lane = tid & 31;
    if (warp >= N_NODES) return;
    const float* hr = &g_h2[(size_t)warp * 128];
    const float* mr = &sme[lane * 129];
    float acc = 0.f;
    #pragma unroll
    for (int k4 = 0; k4 < 32; ++k4) {
        float4 v = *(const float4*)&hr[k4 * 4];
        acc += v.x * mr[k4 * 4 + 0];
        acc += v.y * mr[k4 * 4 + 1];
        acc += v.z * mr[k4 * 4 + 2];
        acc += v.w * mr[k4 * 4 + 3];
    }
    out[(size_t)warp * 32 + lane] = acc;
}

// ---------------- per-column stats + finalize ----------------
__global__ void k_colstats(const float* __restrict__ sc)
{
    __shared__ float red[256];
    int b = blockIdx.x, tid = threadIdx.x;
    float m = -INFINITY;
    for (int i = tid; i < N_NODES; i += 256)
        m = fmaxf(m, sc[(size_t)i * 32 + b]);
    red[tid] = m; __syncthreads();
    for (int off = 128; off > 0; off >>= 1) {
        if (tid < off) red[tid] = fmaxf(red[tid], red[tid + off]);
        __syncthreads();
    }
    float M = red[0];
    __syncthreads();
    float s = 0.f;
    for (int i = tid; i < N_NODES; i += 256)
        s += __expf(sc[(size_t)i * 32 + b] - M);
    red[tid] = s; __syncthreads();
    for (int off = 128; off > 0; off >>= 1) {
        if (tid < off) red[tid] += red[tid + off];
        __syncthreads();
    }
    if (tid == 0) {
        g_stats[b]      = M;
        g_stats[32 + b] = logf(red[0]);
    }
}

__global__ void k_finalize(float* __restrict__ out)
{
    int i = blockIdx.x * blockDim.x + threadIdx.x;
    if (i < N_NODES * 32) {
        int b = i & 31;
        out[i] = out[i] - g_stats[b] - g_stats[32 + b];
    }
}

// ---------------- launch ----------------
extern "C" void kernel_launch(void* const* d_in, const int* in_sizes, int n_in,
                              void* d_out, int out_size)
{
    const float* x       = (const float*)d_in[0];
    const void*  eidxraw = (const void*)d_in[1];
    const float* lh      = (const float*)d_in[2];
    const float* W1_rel  = (const float*)d_in[3];
    const float* W1_root = (const float*)d_in[4];
    const float* b1      = (const float*)d_in[5];
    const float* W2_rel  = (const float*)d_in[6];
    const float* W2_root = (const float*)d_in[7];
    const float* b2      = (const float*)d_in[8];
    const float* Wp      = (const float*)d_in[9];
    const float* bp      = (const float*)d_in[10];
    float*       out     = (float*)d_out;

    const int GEMM_T = (N_NODES + 127) / 128;
    const int WARP_G = (N_NODES * 32 + 255) / 256;

    // CSR build (hierarchical scan)
    k_zero_deg<<<(N_NODES + 255) / 256, 256>>>();
    k_detect<<<1, 256>>>((const unsigned int*)eidxraw);
    k_convert_count<<<(2 * N_EDGES + 255) / 256, 256>>>(eidxraw);
    k_blocksum<<<SCAN_G, SCAN_B>>>();
    k_scanbsum<<<1, SCAN_B>>>();
    k_scatter_rows<<<SCAN_G, SCAN_B>>>();
    k_fill<<<(N_EDGES + 255) / 256, 256>>>();

    // layer 1
    k_gather<<<WARP_G, 256>>>(x, 0);
    k_layer_gemm<<<GEMM_T, 256>>>(x, W1_rel, W1_root, b1, 0, 0, N_NODES);
    // layer 2
    k_gather<<<WARP_G, 256>>>(x, 1);
    k_layer_gemm<<<GEMM_T, 256>>>(x, W2_rel, W2_root, b2, 1, 1, N_NODES);

    // projection + scores + log_softmax(axis=0)
    k_proj<<<16, 256>>>(lh, Wp, bp);
    k_scores<<<WARP_G, 256>>>(out);
    k_colstats<<<32, 256>>>(out);
    k_finalize<<<(N_NODES * 32 + 255) / 256, 256>>>(out);
}

// round 12
// speedup vs baseline: 1.6615x; 1.2160x over previous
#include <cuda_runtime.h>
#include <cuda_bf16.h>
#include <math.h>
#include <stdint.h>

#define N_NODES 50000
#define N_EDGES 640000
#define FEAT    128
#define HIDDEN  512
#define BATCH   32

#define SCAN_B 256
#define SCAN_G ((N_NODES + SCAN_B - 1) / SCAN_B)   // 196

// ---------------- scratch (static device globals; no allocation) ----------------
__device__ float g_agg[(size_t)N_NODES * FEAT];
__device__ float g_h[(size_t)N_NODES * FEAT];
__device__ float g_h2[(size_t)N_NODES * FEAT];
__device__ int   g_eidx[2 * N_EDGES];
__device__ int   g_is64;
__device__ int   g_degi[N_NODES];
__device__ int   g_bsum[SCAN_G];
__device__ int   g_rowstart[N_NODES + 1];
__device__ int   g_cursor[N_NODES];
__device__ int   g_csr[N_EDGES];
__device__ float g_me[BATCH * FEAT];
__device__ float g_stats[64];
// pre-split stacked weights: [layer][hi/lo][k(256) * n(128)] bf16, k-major rows
__device__ __nv_bfloat16 g_wsplit[2][2][256 * 128];

__device__ __forceinline__ uint32_t smem_u32(const void* p) {
    uint32_t a;
    asm("{ .reg .u64 t; cvta.to.shared.u64 t, %1; cvt.u32.u64 %0, t; }" : "=r"(a) : "l"(p));
    return a;
}

// ---------------- detect dtype + zero degrees (merged) ----------------
__global__ void k_detect_zero(const unsigned int* __restrict__ raw) {
    int i = blockIdx.x * blockDim.x + threadIdx.x;
    if (i < N_NODES) g_degi[i] = 0;
    if (blockIdx.x == 0) {
        __shared__ int any_nz;
        if (threadIdx.x == 0) any_nz = 0;
        __syncthreads();
        int nz = 0;
        for (int p = threadIdx.x; p < 2048; p += 256)
            if (raw[2 * p + 1] != 0u) nz = 1;
        if (nz) atomicOr(&any_nz, 1);
        __syncthreads();
        if (threadIdx.x == 0) g_is64 = any_nz ? 0 : 1;
    }
}

// convert + count fused
__global__ void k_convert_count(const void* __restrict__ raw) {
    int e = blockIdx.x * blockDim.x + threadIdx.x;
    if (e >= 2 * N_EDGES) return;
    long long v;
    if (g_is64) v = ((const long long*)raw)[e];
    else        v = (long long)(((const int*)raw)[e]);
    int iv = (int)v;
    if (iv < 0) iv = 0;
    if (iv >= N_NODES) iv = N_NODES - 1;
    g_eidx[e] = iv;
    if (e >= N_EDGES) atomicAdd(&g_degi[iv], 1);
}

// ---------------- hierarchical scan ----------------
__global__ void k_blocksum() {
    __shared__ int red[SCAN_B];
    int i = blockIdx.x * SCAN_B + threadIdx.x;
    red[threadIdx.x] = (i < N_NODES) ? g_degi[i] : 0;
    __syncthreads();
    for (int off = SCAN_B / 2; off > 0; off >>= 1) {
        if (threadIdx.x < off) red[threadIdx.x] += red[threadIdx.x + off];
        __syncthreads();
    }
    if (threadIdx.x == 0) g_bsum[blockIdx.x] = red[0];
}

__global__ void k_scatter_rows() {
    __shared__ int wsum[8];
    __shared__ int boff;
    int tid = threadIdx.x;
    // block offset = sum of prior block sums (deterministic int atomics)
    if (tid == 0) boff = 0;
    __syncthreads();
    if (tid < (int)blockIdx.x) atomicAdd(&boff, g_bsum[tid]);
    int i = blockIdx.x * SCAN_B + tid;
    int lane = tid & 31, wid = tid >> 5;
    int d = (i < N_NODES) ? g_degi[i] : 0;
    int v = d;
    #pragma unroll
    for (int off = 1; off < 32; off <<= 1) {
        int t = __shfl_up_sync(0xffffffffu, v, off);
        if (lane >= off) v += t;
    }
    if (lane == 31) wsum[wid] = v;
    __syncthreads();
    if (wid == 0 && lane < 8) {
        int w = wsum[lane];
        #pragma unroll
        for (int off = 1; off < 8; off <<= 1) {
            int t = __shfl_up_sync(0xffu, w, off);
            if (lane >= off) w += t;
        }
        wsum[lane] = w;
    }
    __syncthreads();
    int excl = v - d + (wid > 0 ? wsum[wid - 1] : 0) + boff;
    if (i < N_NODES) {
        g_rowstart[i] = excl;
        g_cursor[i]   = excl;
    }
    if (i == N_NODES - 1) g_rowstart[N_NODES] = excl + d;
}

__global__ void k_fill() {
    int e = blockIdx.x * blockDim.x + threadIdx.x;
    if (e < N_EDGES) {
        int d = g_eidx[N_EDGES + e];
        int pos = atomicAdd(&g_cursor[d], 1);
        if (pos >= 0 && pos < N_EDGES) g_csr[pos] = g_eidx[e];
    }
}

// ---------------- weight pre-split: stacked [Wrel; Wroot] -> bf16 hi/lo planes --------
__global__ void k_prep_w(const float* __restrict__ W1r, const float* __restrict__ W1o,
                         const float* __restrict__ W2r, const float* __restrict__ W2o)
{
    int idx = blockIdx.x * blockDim.x + threadIdx.x;   // 0 .. 2*256*128-1
    if (idx >= 2 * 256 * 128) return;
    int l = idx >> 15;
    int e = idx & 32767;
    int k = e >> 7, n = e & 127;
    const float* W = (k < 128) ? (l ? W2r : W1r) : (l ? W2o : W1o);
    float v = W[(size_t)(k & 127) * 128 + n];
    __nv_bfloat16 h = __float2bfloat16(v);
    __nv_bfloat16 lo = __float2bfloat16(v - __bfloat162float(h));
    g_wsplit[l][0][e] = h;
    g_wsplit[l][1][e] = lo;
}

// ---------------- gather: g_agg[d] = mean over src of base[src] ----------------
__global__ void k_gather(const float* __restrict__ base, int from_h)
{
    const float* B = from_h ? (const float*)g_h : base;
    int warp = (blockIdx.x * blockDim.x + threadIdx.x) >> 5;
    int lane = threadIdx.x & 31;
    if (warp >= N_NODES) return;
    int beg = g_rowstart[warp];
    int end = g_rowstart[warp + 1];
    float4 acc = make_float4(0.f, 0.f, 0.f, 0.f);
    for (int j = beg; j < end; ++j) {
        int s = g_csr[j];
        float4 v = *(const float4*)&B[(size_t)s * 128 + lane * 4];
        acc.x += v.x; acc.y += v.y; acc.z += v.z; acc.w += v.w;
    }
    float invd = 1.0f / fmaxf((float)(end - beg), 1.0f);
    acc.x *= invd; acc.y *= invd; acc.z *= invd; acc.w *= invd;
    *(float4*)&g_agg[(size_t)warp * 128 + lane * 4] = acc;
}

// ---------------- mma.sync helpers ----------------
__device__ __forceinline__ void hmma16816(float* c, const uint32_t* a,
                                          uint32_t b0, uint32_t b1) {
    asm volatile(
        "mma.sync.aligned.m16n8k16.row.col.f32.bf16.bf16.f32 "
        "{%0,%1,%2,%3}, {%4,%5,%6,%7}, {%8,%9}, {%0,%1,%2,%3};"
        : "+f"(c[0]), "+f"(c[1]), "+f"(c[2]), "+f"(c[3])
        : "r"(a[0]), "r"(a[1]), "r"(a[2]), "r"(a[3]), "r"(b0), "r"(b1));
}
__device__ __forceinline__ void ldsm_x4(uint32_t* r, uint32_t addr) {
    asm volatile("ldmatrix.sync.aligned.m8n8.x4.shared.b16 {%0,%1,%2,%3}, [%4];"
                 : "=r"(r[0]), "=r"(r[1]), "=r"(r[2]), "=r"(r[3]) : "r"(addr));
}
__device__ __forceinline__ void ldsm_x4t(uint32_t* r, uint32_t addr) {
    asm volatile("ldmatrix.sync.aligned.m8n8.x4.trans.shared.b16 {%0,%1,%2,%3}, [%4];"
                 : "=r"(r[0]), "=r"(r[1]), "=r"(r[2]), "=r"(r[3]) : "r"(addr));
}
__device__ __forceinline__ void split_bf16(float v, __nv_bfloat16& h, __nv_bfloat16& l) {
    h = __float2bfloat16(v);
    l = __float2bfloat16(v - __bfloat162float(h));
}

// ---------------- fused layer GEMM ----------------
// h_out = relu([agg | h_in] @ Wstack + b), K=256, N=128; bf16-split 3-product.
#define SP_A 40
#define SP_B 136
__global__ __launch_bounds__(256, 2) void k_layer_gemm(
    const float* __restrict__ Hext,
    const float* __restrict__ bias,
    int layer, int h_sel, int c_sel, int M)
{
    __shared__ __nv_bfloat16 sA[2][128 * SP_A];
    __shared__ __nv_bfloat16 sB[2][32 * SP_B];

    const float* Hin = h_sel ? (const float*)g_h : Hext;
    float*       C   = c_sel ? g_h2 : g_h;
    int tid = threadIdx.x;
    int wid = tid >> 5, lane = tid & 31;
    int row0 = blockIdx.x * 128;
    int warp_m = wid >> 1, warp_n = wid & 1;
    int wrow = warp_m * 32;
    int wcol = warp_n * 64;

    uint32_t a_base = smem_u32(&sA[0][0]);
    uint32_t b_base = smem_u32(&sB[0][0]);
    const uint32_t A_IMG = 128 * SP_A * 2;
    const uint32_t B_IMG = 32 * SP_B * 2;
    int a_lr    = lane & 7;
    int a_half  = (lane >> 3) & 1;
    int a_khalf = lane >> 4;
    uint32_t a_off0 = (uint32_t)(wrow + a_lr + a_half * 8) * (SP_A * 2) + (uint32_t)a_khalf * 16;
    int b_lr = lane & 15;
    int b_csel = lane >> 4;           // which 8-col group within x4.trans

    const __nv_bfloat16* Whi = g_wsplit[layer][0];
    const __nv_bfloat16* Wlo = g_wsplit[layer][1];

    float acc[2][8][4];
    #pragma unroll
    for (int mb = 0; mb < 2; ++mb)
        #pragma unroll
        for (int nb = 0; nb < 8; ++nb)
            #pragma unroll
            for (int q = 0; q < 4; ++q) acc[mb][nb][q] = 0.f;

    for (int c = 0; c < 8; ++c) {
        int k0 = c * 32;
        const float* Asrc = (k0 < 128) ? (const float*)g_agg : Hin;
        int ka = k0 & 127;

        // stage A chunk: 128 rows x 32 k, float4 loads + split
        #pragma unroll
        for (int it = 0; it < 4; ++it) {
            int idx = tid + it * 256;              // 0..1023
            int m  = idx >> 3;
            int k4 = (idx & 7) * 4;
            int gr = row0 + m;
            float4 v = make_float4(0.f, 0.f, 0.f, 0.f);
            if (gr < M) v = *(const float4*)&Asrc[(size_t)gr * 128 + ka + k4];
            float vv[4] = {v.x, v.y, v.z, v.w};
            uint32_t hw[2], lw[2];
            #pragma unroll
            for (int p2 = 0; p2 < 2; ++p2) {
                __nv_bfloat16 h0, l0, h1, l1;
                split_bf16(vv[p2 * 2 + 0], h0, l0);
                split_bf16(vv[p2 * 2 + 1], h1, l1);
                hw[p2] = (uint32_t)__bfloat16_as_ushort(h0) | ((uint32_t)__bfloat16_as_ushort(h1) << 16);
                lw[p2] = (uint32_t)__bfloat16_as_ushort(l0) | ((uint32_t)__bfloat16_as_ushort(l1) << 16);
            }
            uint32_t doff = (uint32_t)m * (SP_A * 2) + (uint32_t)k4 * 2;
            *(uint2*)((char*)&sA[0][0] + doff) = make_uint2(hw[0], hw[1]);
            *(uint2*)((char*)&sA[1][0] + doff) = make_uint2(lw[0], lw[1]);
        }
        // stage B chunk: pure copy of pre-split planes (32 k x 128 n)
        #pragma unroll
        for (int it = 0; it < 4; ++it) {
            int idx = tid + it * 256;              // 0..1023
            int kk = idx >> 5;
            int n4 = (idx & 31) * 4;
            uint32_t soff = (uint32_t)(k0 + kk) * 128 + (uint32_t)n4;
            uint32_t doff = (uint32_t)kk * (SP_B * 2) + (uint32_t)n4 * 2;
            *(uint2*)((char*)&sB[0][0] + doff) = *(const uint2*)&Whi[soff];
            *(uint2*)((char*)&sB[1][0] + doff) = *(const uint2*)&Wlo[soff];
        }
        __syncthreads();

        #pragma unroll
        for (int kk = 0; kk < 2; ++kk) {
            uint32_t ah[2][4], al[2][4];
            #pragma unroll
            for (int mb = 0; mb < 2; ++mb) {
                uint32_t ao = a_off0 + (uint32_t)(mb * 16) * (SP_A * 2) + (uint32_t)kk * 32;
                ldsm_x4(ah[mb], a_base + 0 * A_IMG + ao);
                ldsm_x4(al[mb], a_base + 1 * A_IMG + ao);
            }
            uint32_t b_row = (uint32_t)(kk * 16 + b_lr) * (SP_B * 2);
            #pragma unroll
            for (int nb2 = 0; nb2 < 4; ++nb2) {
                uint32_t bh[4], bl[4];
                uint32_t bcol = (uint32_t)(wcol + nb2 * 16 + b_csel * 8) * 2;
                ldsm_x4t(bh, b_base + 0 * B_IMG + b_row + bcol);
                ldsm_x4t(bl, b_base + 1 * B_IMG + b_row + bcol);
                #pragma unroll
                for (int hh = 0; hh < 2; ++hh) {
                    int nb = nb2 * 2 + hh;
                    #pragma unroll
                    for (int mb = 0; mb < 2; ++mb) {
                        hmma16816(acc[mb][nb], ah[mb], bh[2 * hh], bh[2 * hh + 1]);
                        hmma16816(acc[mb][nb], ah[mb], bl[2 * hh], bl[2 * hh + 1]);
                        hmma16816(acc[mb][nb], al[mb], bh[2 * hh], bh[2 * hh + 1]);
                    }
                }
            }
        }
        __syncthreads();
    }

    int g   = lane >> 2;
    int tig = lane & 3;
    #pragma unroll
    for (int nb = 0; nb < 8; ++nb) {
        int col = wcol + nb * 8 + tig * 2;
        float bb0 = bias[col], bb1 = bias[col + 1];
        #pragma unroll
        for (int mb = 0; mb < 2; ++mb) {
            int r0g = row0 + wrow + mb * 16 + g;
            int r1g = r0g + 8;
            float* a = acc[mb][nb];
            if (r0g < M)
                *(float2*)&C[(size_t)r0g * 128 + col] =
                    make_float2(fmaxf(a[0] + bb0, 0.f), fmaxf(a[1] + bb1, 0.f));
            if (r1g < M)
                *(float2*)&C[(size_t)r1g * 128 + col] =
                    make_float2(fmaxf(a[2] + bb0, 0.f), fmaxf(a[3] + bb1, 0.f));
        }
    }
}

// ---------------- projection ----------------
__global__ void k_proj(const float* __restrict__ lh, const float* __restrict__ Wp,
                       const float* __restrict__ bp)
{
    int idx = blockIdx.x * blockDim.x + threadIdx.x;
    if (idx >= BATCH * 128) return;
    int b = idx >> 7, j = idx & 127;
    float acc = bp[j];
    const float* lr = &lh[(size_t)b * HIDDEN];
    #pragma unroll 8
    for (int k = 0; k < HIDDEN; ++k)
        acc += lr[k] * Wp[(size_t)k * 128 + j];
    g_me[b * 128 + j] = acc;
}

// ---------------- scores ----------------
__global__ void k_scores(float* __restrict__ out)
{
    __shared__ float sme[32 * 129];
    int tid = threadIdx.x;
    for (int idx = tid; idx < 32 * 128; idx += blockDim.x) {
        int b = idx >> 7, k = idx & 127;
        sme[b * 129 + k] = g_me[idx];
    }
    __syncthreads();
    int warp = (blockIdx.x * blockDim.x + tid) >> 5;
    int lane = tid & 31;
    if (warp >= N_NODES) return;
    const float* hr = &g_h2[(size_t)warp * 128];
    const float* mr = &sme[lane * 129];
    float acc = 0.f;
    #pragma unroll
    for (int k4 = 0; k4 < 32; ++k4) {
        float4 v = *(const float4*)&hr[k4 * 4];
        acc += v.x * mr[k4 * 4 + 0];
        acc += v.y * mr[k4 * 4 + 1];
        acc += v.z * mr[k4 * 4 + 2];
        acc += v.w * mr[k4 * 4 + 3];
    }
    out[(size_t)warp * 32 + lane] = acc;
}

// ---------------- per-column stats + finalize ----------------
__global__ void k_colstats(const float* __restrict__ sc)
{
    __shared__ float red[256];
    int b = blockIdx.x, tid = threadIdx.x;
    float m = -INFINITY;
    for (int i = tid; i < N_NODES; i += 256)
        m = fmaxf(m, sc[(size_t)i * 32 + b]);
    red[tid] = m; __syncthreads();
    for (int off = 128; off > 0; off >>= 1) {
        if (tid < off) red[tid] = fmaxf(red[tid], red[tid + off]);
        __syncthreads();
    }
    float M = red[0];
    __syncthreads();
    float s = 0.f;
    for (int i = tid; i < N_NODES; i += 256)
        s += __expf(sc[(size_t)i * 32 + b] - M);
    red[tid] = s; __syncthreads();
    for (int off = 128; off > 0; off >>= 1) {
        if (tid < off) red[tid] += red[tid + off];
        __syncthreads();
    }
    if (tid == 0) {
        g_stats[b]      = M;
        g_stats[32 + b] = logf(red[0]);
    }
}

__global__ void k_finalize(float* __restrict__ out)
{
    int i = blockIdx.x * blockDim.x + threadIdx.x;
    if (i < N_NODES * 32) {
        int b = i & 31;
        out[i] = out[i] - g_stats[b] - g_stats[32 + b];
    }
}

// ---------------- launch ----------------
extern "C" void kernel_launch(void* const* d_in, const int* in_sizes, int n_in,
                              void* d_out, int out_size)
{
    const float* x       = (const float*)d_in[0];
    const void*  eidxraw = (const void*)d_in[1];
    const float* lh      = (const float*)d_in[2];
    const float* W1_rel  = (const float*)d_in[3];
    const float* W1_root = (const float*)d_in[4];
    const float* b1      = (const float*)d_in[5];
    const float* W2_rel  = (const float*)d_in[6];
    const float* W2_root = (const float*)d_in[7];
    const float* b2      = (const float*)d_in[8];
    const float* Wp      = (const float*)d_in[9];
    const float* bp      = (const float*)d_in[10];
    float*       out     = (float*)d_out;

    const int GEMM_T = (N_NODES + 127) / 128;
    const int WARP_G = (N_NODES * 32 + 255) / 256;

    // CSR build
    k_detect_zero<<<SCAN_G, SCAN_B>>>((const unsigned int*)eidxraw);
    k_convert_count<<<(2 * N_EDGES + 255) / 256, 256>>>(eidxraw);
    k_blocksum<<<SCAN_G, SCAN_B>>>();
    k_scatter_rows<<<SCAN_G, SCAN_B>>>();
    k_fill<<<(N_EDGES + 255) / 256, 256>>>();

    // weight pre-split (independent of CSR)
    k_prep_w<<<(2 * 256 * 128 + 255) / 256, 256>>>(W1_rel, W1_root, W2_rel, W2_root);

    // layer 1
    k_gather<<<WARP_G, 256>>>(x, 0);
    k_layer_gemm<<<GEMM_T, 256>>>(x, b1, 0, 0, 0, N_NODES);
    // layer 2
    k_gather<<<WARP_G, 256>>>(x, 1);
    k_layer_gemm<<<GEMM_T, 256>>>(x, b2, 1, 1, 1, N_NODES);

    // projection + scores + log_softmax(axis=0)
    k_proj<<<16, 256>>>(lh, Wp, bp);
    k_scores<<<WARP_G, 256>>>(out);
    k_colstats<<<32, 256>>>(out);
    k_finalize<<<(N_NODES * 32 + 255) / 256, 256>>>(out);
}